// round 9
// baseline (speedup 1.0000x reference)
#include <cuda_runtime.h>
#include <stdint.h>

#define B 16
#define N 4096
#define F 128
#define K 1024
#define ROWS_PER_CTA 8
#define ADJ_BLOCKS ((B * K) / ROWS_PER_CTA)   // 2048
#define HB 11
#define NB (1 << HB)   // 2048 histogram buckets

typedef unsigned long long u64;
typedef unsigned int u32;

// scratch (no allocations allowed)
__device__ float g_scores[B * N];
__device__ int   g_topk_idx[B * K];
__device__ float g_topk_val[B * K];
__device__ int   g_scol[B * K];   // selected columns sorted ascending
__device__ int   g_spos[B * K];   // original top-k position of that column

__device__ __forceinline__ unsigned map_f32(float f) {
    unsigned u = __float_as_uint(f);
    return (u & 0x80000000u) ? ~u : (u | 0x80000000u);
}

// ---------------------------------------------------------------------------
// Kernel 1: scores, persistent grid-stride. One warp per 4-row group per
// iteration; independent iterations keep the DRAM queue full without churn.
// ---------------------------------------------------------------------------
__global__ void scores_kernel(const float* __restrict__ ne,
                              const float* __restrict__ w) {
    const int lane  = threadIdx.x & 31;
    const int gwarp = (blockIdx.x * blockDim.x + threadIdx.x) >> 5;
    const int nwarp = (gridDim.x * blockDim.x) >> 5;
    const float4* wv = reinterpret_cast<const float4*>(w);
    const float4 b4 = wv[lane];

#pragma unroll 2
    for (int g = gwarp; g < (B * N) / 4; g += nwarp) {
        int row0 = g * 4;
        const float4* r0 = reinterpret_cast<const float4*>(ne + (size_t)row0 * F);
        const float4* r1 = reinterpret_cast<const float4*>(ne + (size_t)(row0 + 1) * F);
        const float4* r2 = reinterpret_cast<const float4*>(ne + (size_t)(row0 + 2) * F);
        const float4* r3 = reinterpret_cast<const float4*>(ne + (size_t)(row0 + 3) * F);
        float4 a0 = r0[lane], a1 = r1[lane], a2 = r2[lane], a3 = r3[lane];

        float s0 = a0.x * b4.x + a0.y * b4.y + a0.z * b4.z + a0.w * b4.w;
        float s1 = a1.x * b4.x + a1.y * b4.y + a1.z * b4.z + a1.w * b4.w;
        float s2 = a2.x * b4.x + a2.y * b4.y + a2.z * b4.z + a2.w * b4.w;
        float s3 = a3.x * b4.x + a3.y * b4.y + a3.z * b4.z + a3.w * b4.w;
#pragma unroll
        for (int off = 16; off; off >>= 1) {
            s0 += __shfl_xor_sync(0xffffffffu, s0, off);
            s1 += __shfl_xor_sync(0xffffffffu, s1, off);
            s2 += __shfl_xor_sync(0xffffffffu, s2, off);
            s3 += __shfl_xor_sync(0xffffffffu, s3, off);
        }
        if (lane == 0)
            *reinterpret_cast<float4*>(g_scores + row0) =
                make_float4(s0, s1, s2, s3);
    }
}

// ---------------------------------------------------------------------------
// Kernel 2: radix-select + hybrid register/smem bitonic sort.
// key = (monotonic(score) << 12) | (4095 - idx) -> desc sort == jax top_k order
// ---------------------------------------------------------------------------
__device__ __forceinline__ u64 u64max(u64 a, u64 b) { return a > b ? a : b; }
__device__ __forceinline__ u64 u64min(u64 a, u64 b) { return a < b ? a : b; }

__device__ __forceinline__ void reg_stages(u64& e0, u64& e1, int i0, int i1,
                                           int lane, int kk) {
    if (kk >= 64) {
        bool desc = ((i0 & kk) == 0);
        if (desc ? (e0 < e1) : (e0 > e1)) { u64 t = e0; e0 = e1; e1 = t; }
    }
#pragma unroll
    for (int j = 16; j >= 1; j >>= 1) {
        if (j <= (kk >> 1)) {
            bool d0 = ((i0 & kk) == 0);
            bool d1 = ((i1 & kk) == 0);
            bool up = (lane & j) != 0;
            u64 p0 = __shfl_xor_sync(0xffffffffu, e0, j);
            u64 p1 = __shfl_xor_sync(0xffffffffu, e1, j);
            e0 = (d0 ^ up) ? u64max(e0, p0) : u64min(e0, p0);
            e1 = (d1 ^ up) ? u64max(e1, p1) : u64min(e1, p1);
        }
    }
}

__global__ void __launch_bounds__(1024) topk_kernel() {
    __shared__ u64 cand[4096];       // 32 KB
    __shared__ int hist[NB];         //  8 KB (reused as bitmap later)
    __shared__ int wsum[32];
    __shared__ int s_t0, s_cnt;

    const int b    = blockIdx.x;
    const int tid  = threadIdx.x;
    const int lane = tid & 31;
    const int warp = tid >> 5;
    const float* sc = g_scores + b * N;

    hist[tid] = 0;
    hist[tid + 1024] = 0;
    __syncthreads();

    u64 kreg[4];
#pragma unroll
    for (int q = 0; q < 4; q++) {
        int i = tid + q * 1024;
        unsigned m = map_f32(sc[i]);
        kreg[q] = (((u64)m) << 12) | (unsigned)(N - 1 - i);
        // warp-aggregated histogram update (hot buckets otherwise serialize)
        unsigned bkt = m >> (32 - HB);
        unsigned peers = __match_any_sync(0xffffffffu, bkt);
        int leader = __ffs(peers) - 1;
        if (lane == leader) atomicAdd(&hist[bkt], __popc(peers));
    }
    __syncthreads();

    // ---- cutoff bucket t0 = max t such that count(bucket >= t) >= K ----
    {
        int p = hist[2 * tid] + hist[2 * tid + 1];
        int ws = p;
#pragma unroll
        for (int off = 16; off; off >>= 1)
            ws += __shfl_xor_sync(0xffffffffu, ws, off);
        if (lane == 0) wsum[warp] = ws;
    }
    __syncthreads();
    if (warp == 0) {
        int v = wsum[lane];
        int s = v;
#pragma unroll
        for (int off = 1; off < 32; off <<= 1) {
            int t = __shfl_down_sync(0xffffffffu, s, off);
            if (lane + off < 32) s += t;
        }
        unsigned mm = __ballot_sync(0xffffffffu, s >= K);
        int wstar = 31 - __clz(mm);
        int sW = __shfl_sync(0xffffffffu, s, wstar);
        int vW = __shfl_sync(0xffffffffu, v, wstar);
        int run = sW - vW;
        int segbase = wstar * 64;
        int t0 = 0;
#pragma unroll
        for (int c = 1; c >= 0; c--) {
            int bkt = segbase + c * 32 + lane;
            int hv = hist[bkt];
            int s2 = hv;
#pragma unroll
            for (int off = 1; off < 32; off <<= 1) {
                int t = __shfl_down_sync(0xffffffffu, s2, off);
                if (lane + off < 32) s2 += t;
            }
            unsigned m2 = __ballot_sync(0xffffffffu, run + s2 >= K);
            if (m2) { t0 = segbase + c * 32 + (31 - __clz(m2)); break; }
            run += __shfl_sync(0xffffffffu, s2, 0);
        }
        if (lane == 0) { s_t0 = t0; s_cnt = 0; }
    }
    __syncthreads();

    // ---- compact candidates (bucket >= t0), warp-aggregated atomics ----
    int t0 = s_t0;
#pragma unroll
    for (int q = 0; q < 4; q++) {
        bool p = (int)(kreg[q] >> 33) >= t0;
        unsigned mask = __ballot_sync(0xffffffffu, p);
        int cnt = __popc(mask);
        int base = 0;
        if (lane == 0 && cnt) base = atomicAdd(&s_cnt, cnt);
        base = __shfl_sync(0xffffffffu, base, 0);
        if (p) cand[base + __popc(mask & ((1u << lane) - 1u))] = kreg[q];
    }
    __syncthreads();
    int M = s_cnt;

    if (M <= 2048) {
        for (int i = M + tid; i < 2048; i += 1024) cand[i] = 0;
        __syncthreads();

        const int base = warp * 64;
        const int i0 = base + lane, i1 = base + 32 + lane;
        u64 e0, e1;

        e0 = cand[i0]; e1 = cand[i1];
#pragma unroll
        for (int kk = 2; kk <= 64; kk <<= 1)
            reg_stages(e0, e1, i0, i1, lane, kk);
        cand[i0] = e0; cand[i1] = e1;
        __syncthreads();

#pragma unroll
        for (int kk = 128; kk <= 2048; kk <<= 1) {
            for (int j = kk >> 1; j >= 64; j >>= 1) {
                int i = 2 * tid - (tid & (j - 1));
                int x = i + j;
                bool desc = ((i & kk) == 0);
                u64 a = cand[i], c = cand[x];
                if (desc ? (a < c) : (a > c)) { cand[i] = c; cand[x] = a; }
                __syncthreads();
            }
            e0 = cand[i0]; e1 = cand[i1];
            reg_stages(e0, e1, i0, i1, lane, kk);
            cand[i0] = e0; cand[i1] = e1;
            __syncthreads();
        }
    } else {
        // safety fallback: plain full bitonic over all 4096 keys
#pragma unroll
        for (int q = 0; q < 4; q++) cand[tid + q * 1024] = kreg[q];
        __syncthreads();
        for (int kk = 2; kk <= 4096; kk <<= 1) {
            for (int j = kk >> 1; j > 0; j >>= 1) {
                for (int q = tid; q < 2048; q += 1024) {
                    int i = 2 * q - (q & (j - 1));
                    int x = i + j;
                    bool desc = ((i & kk) == 0);
                    u64 a = cand[i], c = cand[x];
                    if (desc ? (a < c) : (a > c)) { cand[i] = c; cand[x] = a; }
                }
                __syncthreads();
            }
        }
    }

    // ---- emit top-K (sorted desc) ----
    u64 key = cand[tid];
    int idx = (N - 1) - (int)(key & 0xFFFu);
    unsigned m = (unsigned)(key >> 12);
    unsigned u = (m & 0x80000000u) ? (m ^ 0x80000000u) : ~m;
    g_topk_idx[b * K + tid] = idx;
    g_topk_val[b * K + tid] = __uint_as_float(u);

    // ---- column-ascending permutation via bitmap counting-rank ----
    u32* bits = (u32*)hist;           // 4096-bit presence bitmap
    int* wordpref = hist + 128;
    if (tid < 128) bits[tid] = 0;
    __syncthreads();
    atomicOr(&bits[idx >> 5], 1u << (idx & 31));
    __syncthreads();
    if (warp == 0) {
        int s0 = __popc(bits[4 * lane]);
        int s1 = __popc(bits[4 * lane + 1]);
        int s2 = __popc(bits[4 * lane + 2]);
        int s3 = __popc(bits[4 * lane + 3]);
        int tot = s0 + s1 + s2 + s3;
        int ex = tot;
#pragma unroll
        for (int off = 1; off < 32; off <<= 1) {
            int t = __shfl_up_sync(0xffffffffu, ex, off);
            if (lane >= off) ex += t;
        }
        ex -= tot;
        wordpref[4 * lane]     = ex;
        wordpref[4 * lane + 1] = ex + s0;
        wordpref[4 * lane + 2] = ex + s0 + s1;
        wordpref[4 * lane + 3] = ex + s0 + s1 + s2;
    }
    __syncthreads();
    int wrd = idx >> 5, bit = idx & 31;
    int rank = wordpref[wrd] + __popc(bits[wrd] & ((1u << bit) - 1u));
    g_scol[b * K + rank] = idx;
    g_spos[b * K + rank] = tid;
}

// ---------------------------------------------------------------------------
// Kernel 3 (fused): blocks [0, ADJ_BLOCKS) adj gather; rest pooled_nodes.
// adj: 2 rows per barrier phase, 4 rotating smem buffers, streaming loads.
// ---------------------------------------------------------------------------
__global__ void __launch_bounds__(256) fused_kernel(const float* __restrict__ ne,
                                                    const float* __restrict__ adj,
                                                    float* __restrict__ out) {
    if (blockIdx.x < ADJ_BLOCKS) {
        __shared__ int   scol[K];
        __shared__ short spos[K];
        __shared__ float buf[4][K];          // two pairs, rotating
        __shared__ int   ridx[ROWS_PER_CTA];

        float* aout = out + (size_t)B * K * F;
        const int b     = blockIdx.x >> 7;             // 128 CTAs per batch
        const int rbase = (blockIdx.x & 127) * ROWS_PER_CTA;
        const int tid   = threadIdx.x;

#pragma unroll
        for (int q = 0; q < 4; q++) {
            int j = tid + q * 256;
            scol[j] = g_scol[b * K + j];
            spos[j] = (short)g_spos[b * K + j];
        }
        if (tid < ROWS_PER_CTA) ridx[tid] = g_topk_idx[b * K + rbase + tid];
        __syncthreads();

        const int c0 = scol[4 * tid],     c1 = scol[4 * tid + 1];
        const int c2 = scol[4 * tid + 2], c3 = scol[4 * tid + 3];
        const int p0 = spos[4 * tid],     p1 = spos[4 * tid + 1];
        const int p2 = spos[4 * tid + 2], p3 = spos[4 * tid + 3];

        // prefetch phase 0 (rows 0,1): 8 outstanding streaming gathers
        float cur[8], nxt[8];
        {
            const float* ra = adj + ((size_t)b * N + ridx[0]) * N;
            const float* rb = adj + ((size_t)b * N + ridx[1]) * N;
            cur[0] = __ldcs(ra + c0); cur[1] = __ldcs(ra + c1);
            cur[2] = __ldcs(ra + c2); cur[3] = __ldcs(ra + c3);
            cur[4] = __ldcs(rb + c0); cur[5] = __ldcs(rb + c1);
            cur[6] = __ldcs(rb + c2); cur[7] = __ldcs(rb + c3);
        }

#pragma unroll
        for (int p = 0; p < ROWS_PER_CTA / 2; p++) {
            if (p + 1 < ROWS_PER_CTA / 2) {
                const float* ra = adj + ((size_t)b * N + ridx[2 * p + 2]) * N;
                const float* rb = adj + ((size_t)b * N + ridx[2 * p + 3]) * N;
                nxt[0] = __ldcs(ra + c0); nxt[1] = __ldcs(ra + c1);
                nxt[2] = __ldcs(ra + c2); nxt[3] = __ldcs(ra + c3);
                nxt[4] = __ldcs(rb + c0); nxt[5] = __ldcs(rb + c1);
                nxt[6] = __ldcs(rb + c2); nxt[7] = __ldcs(rb + c3);
            }
            float* bb0 = buf[2 * (p & 1)];
            float* bb1 = buf[2 * (p & 1) + 1];
            bb0[p0] = cur[0]; bb0[p1] = cur[1]; bb0[p2] = cur[2]; bb0[p3] = cur[3];
            bb1[p0] = cur[4]; bb1[p1] = cur[5]; bb1[p2] = cur[6]; bb1[p3] = cur[7];
            __syncthreads();
            float4 w0 = *reinterpret_cast<float4*>(&bb0[4 * tid]);
            float4 w1 = *reinterpret_cast<float4*>(&bb1[4 * tid]);
            float* o0 = aout + ((size_t)b * K + rbase + 2 * p) * K;
            float* o1 = aout + ((size_t)b * K + rbase + 2 * p + 1) * K;
            *reinterpret_cast<float4*>(o0 + 4 * tid) = w0;
            *reinterpret_cast<float4*>(o1 + 4 * tid) = w1;
#pragma unroll
            for (int z = 0; z < 8; z++) cur[z] = nxt[z];
            // pair (p&1) is re-scattered at phase p+2, after barrier p+1,
            // by which point every thread's phase-p reads are complete: safe.
        }
    } else {
        int blk  = blockIdx.x - ADJ_BLOCKS;              // [0, 2048)
        int warp = (blk * 256 + (int)threadIdx.x) >> 5;  // [0, B*K)
        int lane = threadIdx.x & 31;
        int b    = warp >> 10;
        int idx  = g_topk_idx[warp];
        float g  = tanhf(g_topk_val[warp]);
        const float4* src = reinterpret_cast<const float4*>(
            ne + ((size_t)b * N + idx) * F);
        float4* dst = reinterpret_cast<float4*>(out + (size_t)warp * F);
        float4 v = src[lane];
        v.x *= g; v.y *= g; v.z *= g; v.w *= g;
        dst[lane] = v;
    }
}

// ---------------------------------------------------------------------------
extern "C" void kernel_launch(void* const* d_in, const int* in_sizes, int n_in,
                              void* d_out, int out_size) {
    const float* ne  = (const float*)d_in[0];  // [B,N,F]
    const float* adj = (const float*)d_in[1];  // [B,N,N]
    const float* w   = (const float*)d_in[2];  // [F]
    float* out       = (float*)d_out;

    scores_kernel<<<592, 256>>>(ne, w);        // persistent, 4 CTAs/SM
    topk_kernel<<<B, 1024>>>();
    fused_kernel<<<ADJ_BLOCKS + (B * K) / 8, 256>>>(ne, adj, out);
}

// round 10
// speedup vs baseline: 1.2585x; 1.2585x over previous
#include <cuda_runtime.h>
#include <stdint.h>

#define B 16
#define N 4096
#define F 128
#define K 1024
#define ROWS_PER_CTA 8
#define ADJ_BLOCKS ((B * K) / ROWS_PER_CTA)   // 2048
#define HB 11
#define NB (1 << HB)   // 2048 histogram buckets

typedef unsigned long long u64;
typedef unsigned int u32;

// scratch (no allocations allowed)
__device__ float g_scores[B * N];
__device__ int   g_topk_idx[B * K];
__device__ float g_topk_val[B * K];
__device__ int   g_scol[B * K];   // selected columns sorted ascending
__device__ int   g_spos[B * K];   // original top-k position of that column

__device__ __forceinline__ unsigned map_f32(float f) {
    unsigned u = __float_as_uint(f);
    return (u & 0x80000000u) ? ~u : (u | 0x80000000u);
}

// ---------------------------------------------------------------------------
// Kernel 1: scores. 4 rows per warp -> 4 independent loads in flight per lane.
// (R7 configuration: 2048 CTAs, measured 9.9us)
// ---------------------------------------------------------------------------
__global__ void scores_kernel(const float* __restrict__ ne,
                              const float* __restrict__ w) {
    int warp = (blockIdx.x * blockDim.x + threadIdx.x) >> 5;  // [0, B*N/4)
    int lane = threadIdx.x & 31;
    int row0 = warp * 4;
    if (row0 >= B * N) return;

    const float4* wv = reinterpret_cast<const float4*>(w);
    float4 b4 = wv[lane];
    const float4* r0 = reinterpret_cast<const float4*>(ne + (size_t)row0 * F);
    const float4* r1 = reinterpret_cast<const float4*>(ne + (size_t)(row0 + 1) * F);
    const float4* r2 = reinterpret_cast<const float4*>(ne + (size_t)(row0 + 2) * F);
    const float4* r3 = reinterpret_cast<const float4*>(ne + (size_t)(row0 + 3) * F);
    float4 a0 = r0[lane], a1 = r1[lane], a2 = r2[lane], a3 = r3[lane];

    float s0 = a0.x * b4.x + a0.y * b4.y + a0.z * b4.z + a0.w * b4.w;
    float s1 = a1.x * b4.x + a1.y * b4.y + a1.z * b4.z + a1.w * b4.w;
    float s2 = a2.x * b4.x + a2.y * b4.y + a2.z * b4.z + a2.w * b4.w;
    float s3 = a3.x * b4.x + a3.y * b4.y + a3.z * b4.z + a3.w * b4.w;
#pragma unroll
    for (int off = 16; off; off >>= 1) {
        s0 += __shfl_xor_sync(0xffffffffu, s0, off);
        s1 += __shfl_xor_sync(0xffffffffu, s1, off);
        s2 += __shfl_xor_sync(0xffffffffu, s2, off);
        s3 += __shfl_xor_sync(0xffffffffu, s3, off);
    }
    if (lane == 0)
        *reinterpret_cast<float4*>(g_scores + row0) = make_float4(s0, s1, s2, s3);
}

// ---------------------------------------------------------------------------
// Kernel 2: radix-select + hybrid register/smem bitonic sort.
// key = (monotonic(score) << 12) | (4095 - idx) -> desc sort == jax top_k order
// ---------------------------------------------------------------------------
__device__ __forceinline__ u64 u64max(u64 a, u64 b) { return a > b ? a : b; }
__device__ __forceinline__ u64 u64min(u64 a, u64 b) { return a < b ? a : b; }

__device__ __forceinline__ void reg_stages(u64& e0, u64& e1, int i0, int i1,
                                           int lane, int kk) {
    if (kk >= 64) {
        bool desc = ((i0 & kk) == 0);
        if (desc ? (e0 < e1) : (e0 > e1)) { u64 t = e0; e0 = e1; e1 = t; }
    }
#pragma unroll
    for (int j = 16; j >= 1; j >>= 1) {
        if (j <= (kk >> 1)) {
            bool d0 = ((i0 & kk) == 0);
            bool d1 = ((i1 & kk) == 0);
            bool up = (lane & j) != 0;
            u64 p0 = __shfl_xor_sync(0xffffffffu, e0, j);
            u64 p1 = __shfl_xor_sync(0xffffffffu, e1, j);
            e0 = (d0 ^ up) ? u64max(e0, p0) : u64min(e0, p0);
            e1 = (d1 ^ up) ? u64max(e1, p1) : u64min(e1, p1);
        }
    }
}

__global__ void __launch_bounds__(1024) topk_kernel() {
    __shared__ u64 cand[4096];       // 32 KB
    __shared__ int hist[NB];         //  8 KB (reused as bitmap later)
    __shared__ int wsum[32];
    __shared__ int s_t0, s_cnt;

    const int b    = blockIdx.x;
    const int tid  = threadIdx.x;
    const int lane = tid & 31;
    const int warp = tid >> 5;
    const float* sc = g_scores + b * N;

    hist[tid] = 0;
    hist[tid + 1024] = 0;
    __syncthreads();

    u64 kreg[4];
#pragma unroll
    for (int q = 0; q < 4; q++) {
        int i = tid + q * 1024;
        unsigned m = map_f32(sc[i]);
        kreg[q] = (((u64)m) << 12) | (unsigned)(N - 1 - i);
        // warp-aggregated histogram update: one atomic per distinct bucket
        // per warp (normal-distributed scores make a few buckets very hot,
        // and same-address smem ATOMS serialize at 32 cyc/warp).
        unsigned bkt = m >> (32 - HB);
        unsigned peers = __match_any_sync(0xffffffffu, bkt);
        int leader = __ffs(peers) - 1;
        if (lane == leader) atomicAdd(&hist[bkt], __popc(peers));
    }
    __syncthreads();

    // ---- cutoff bucket t0 = max t such that count(bucket >= t) >= K ----
    {
        int p = hist[2 * tid] + hist[2 * tid + 1];
        int ws = p;
#pragma unroll
        for (int off = 16; off; off >>= 1)
            ws += __shfl_xor_sync(0xffffffffu, ws, off);
        if (lane == 0) wsum[warp] = ws;
    }
    __syncthreads();
    if (warp == 0) {
        int v = wsum[lane];
        int s = v;
#pragma unroll
        for (int off = 1; off < 32; off <<= 1) {
            int t = __shfl_down_sync(0xffffffffu, s, off);
            if (lane + off < 32) s += t;
        }
        unsigned mm = __ballot_sync(0xffffffffu, s >= K);
        int wstar = 31 - __clz(mm);
        int sW = __shfl_sync(0xffffffffu, s, wstar);
        int vW = __shfl_sync(0xffffffffu, v, wstar);
        int run = sW - vW;
        int segbase = wstar * 64;
        int t0 = 0;
#pragma unroll
        for (int c = 1; c >= 0; c--) {
            int bkt = segbase + c * 32 + lane;
            int hv = hist[bkt];
            int s2 = hv;
#pragma unroll
            for (int off = 1; off < 32; off <<= 1) {
                int t = __shfl_down_sync(0xffffffffu, s2, off);
                if (lane + off < 32) s2 += t;
            }
            unsigned m2 = __ballot_sync(0xffffffffu, run + s2 >= K);
            if (m2) { t0 = segbase + c * 32 + (31 - __clz(m2)); break; }
            run += __shfl_sync(0xffffffffu, s2, 0);
        }
        if (lane == 0) { s_t0 = t0; s_cnt = 0; }
    }
    __syncthreads();

    // ---- compact candidates (bucket >= t0), warp-aggregated atomics ----
    int t0 = s_t0;
#pragma unroll
    for (int q = 0; q < 4; q++) {
        bool p = (int)(kreg[q] >> 33) >= t0;
        unsigned mask = __ballot_sync(0xffffffffu, p);
        int cnt = __popc(mask);
        int base = 0;
        if (lane == 0 && cnt) base = atomicAdd(&s_cnt, cnt);
        base = __shfl_sync(0xffffffffu, base, 0);
        if (p) cand[base + __popc(mask & ((1u << lane) - 1u))] = kreg[q];
    }
    __syncthreads();
    int M = s_cnt;

    if (M <= 2048) {
        for (int i = M + tid; i < 2048; i += 1024) cand[i] = 0;
        __syncthreads();

        const int base = warp * 64;
        const int i0 = base + lane, i1 = base + 32 + lane;
        u64 e0, e1;

        e0 = cand[i0]; e1 = cand[i1];
#pragma unroll
        for (int kk = 2; kk <= 64; kk <<= 1)
            reg_stages(e0, e1, i0, i1, lane, kk);
        cand[i0] = e0; cand[i1] = e1;
        __syncthreads();

#pragma unroll
        for (int kk = 128; kk <= 2048; kk <<= 1) {
            for (int j = kk >> 1; j >= 64; j >>= 1) {
                int i = 2 * tid - (tid & (j - 1));
                int x = i + j;
                bool desc = ((i & kk) == 0);
                u64 a = cand[i], c = cand[x];
                if (desc ? (a < c) : (a > c)) { cand[i] = c; cand[x] = a; }
                __syncthreads();
            }
            e0 = cand[i0]; e1 = cand[i1];
            reg_stages(e0, e1, i0, i1, lane, kk);
            cand[i0] = e0; cand[i1] = e1;
            __syncthreads();
        }
    } else {
        // safety fallback: plain full bitonic over all 4096 keys
#pragma unroll
        for (int q = 0; q < 4; q++) cand[tid + q * 1024] = kreg[q];
        __syncthreads();
        for (int kk = 2; kk <= 4096; kk <<= 1) {
            for (int j = kk >> 1; j > 0; j >>= 1) {
                for (int q = tid; q < 2048; q += 1024) {
                    int i = 2 * q - (q & (j - 1));
                    int x = i + j;
                    bool desc = ((i & kk) == 0);
                    u64 a = cand[i], c = cand[x];
                    if (desc ? (a < c) : (a > c)) { cand[i] = c; cand[x] = a; }
                }
                __syncthreads();
            }
        }
    }

    // ---- emit top-K (sorted desc) ----
    u64 key = cand[tid];
    int idx = (N - 1) - (int)(key & 0xFFFu);
    unsigned m = (unsigned)(key >> 12);
    unsigned u = (m & 0x80000000u) ? (m ^ 0x80000000u) : ~m;
    g_topk_idx[b * K + tid] = idx;
    g_topk_val[b * K + tid] = __uint_as_float(u);

    // ---- column-ascending permutation via bitmap counting-rank ----
    u32* bits = (u32*)hist;           // 4096-bit presence bitmap
    int* wordpref = hist + 128;
    if (tid < 128) bits[tid] = 0;
    __syncthreads();
    atomicOr(&bits[idx >> 5], 1u << (idx & 31));
    __syncthreads();
    if (warp == 0) {
        int s0 = __popc(bits[4 * lane]);
        int s1 = __popc(bits[4 * lane + 1]);
        int s2 = __popc(bits[4 * lane + 2]);
        int s3 = __popc(bits[4 * lane + 3]);
        int tot = s0 + s1 + s2 + s3;
        int ex = tot;
#pragma unroll
        for (int off = 1; off < 32; off <<= 1) {
            int t = __shfl_up_sync(0xffffffffu, ex, off);
            if (lane >= off) ex += t;
        }
        ex -= tot;
        wordpref[4 * lane]     = ex;
        wordpref[4 * lane + 1] = ex + s0;
        wordpref[4 * lane + 2] = ex + s0 + s1;
        wordpref[4 * lane + 3] = ex + s0 + s1 + s2;
    }
    __syncthreads();
    int wrd = idx >> 5, bit = idx & 31;
    int rank = wordpref[wrd] + __popc(bits[wrd] & ((1u << bit) - 1u));
    g_scol[b * K + rank] = idx;
    g_spos[b * K + rank] = tid;
}

// ---------------------------------------------------------------------------
// Kernel 3 (fused): blocks [0, ADJ_BLOCKS) adj gather (prefetch depth 2,
// default-cached loads); blocks [ADJ_BLOCKS, ...) pooled_nodes.
// ---------------------------------------------------------------------------
__global__ void __launch_bounds__(256) fused_kernel(const float* __restrict__ ne,
                                                    const float* __restrict__ adj,
                                                    float* __restrict__ out) {
    if (blockIdx.x < ADJ_BLOCKS) {
        __shared__ int   scol[K];
        __shared__ short spos[K];
        __shared__ float buf[2][K];
        __shared__ int   ridx[ROWS_PER_CTA];

        float* aout = out + (size_t)B * K * F;
        const int b     = blockIdx.x >> 7;             // 128 CTAs per batch
        const int rbase = (blockIdx.x & 127) * ROWS_PER_CTA;
        const int tid   = threadIdx.x;

#pragma unroll
        for (int q = 0; q < 4; q++) {
            int j = tid + q * 256;
            scol[j] = g_scol[b * K + j];
            spos[j] = (short)g_spos[b * K + j];
        }
        if (tid < ROWS_PER_CTA) ridx[tid] = g_topk_idx[b * K + rbase + tid];
        __syncthreads();

        const int c0 = scol[4 * tid],     c1 = scol[4 * tid + 1];
        const int c2 = scol[4 * tid + 2], c3 = scol[4 * tid + 3];
        const int p0 = spos[4 * tid],     p1 = spos[4 * tid + 1];
        const int p2 = spos[4 * tid + 2], p3 = spos[4 * tid + 3];

        // prefetch rows 0 and 1 (depth-2 pipeline)
        const float* r0 = adj + ((size_t)b * N + ridx[0]) * N;
        float a0 = __ldg(r0 + c0), a1 = __ldg(r0 + c1);
        float a2 = __ldg(r0 + c2), a3 = __ldg(r0 + c3);
        const float* r1 = adj + ((size_t)b * N + ridx[1]) * N;
        float n0 = __ldg(r1 + c0), n1 = __ldg(r1 + c1);
        float n2 = __ldg(r1 + c2), n3 = __ldg(r1 + c3);

#pragma unroll
        for (int rr = 0; rr < ROWS_PER_CTA; rr++) {
            float m0, m1, m2, m3;
            if (rr + 2 < ROWS_PER_CTA) {
                const float* nr = adj + ((size_t)b * N + ridx[rr + 2]) * N;
                m0 = __ldg(nr + c0); m1 = __ldg(nr + c1);
                m2 = __ldg(nr + c2); m3 = __ldg(nr + c3);
            }
            float* bb = buf[rr & 1];
            bb[p0] = a0; bb[p1] = a1; bb[p2] = a2; bb[p3] = a3;
            __syncthreads();
            float4 w = *reinterpret_cast<float4*>(&bb[4 * tid]);
            float* orow = aout + ((size_t)b * K + rbase + rr) * K;
            *reinterpret_cast<float4*>(orow + 4 * tid) = w;
            a0 = n0; a1 = n1; a2 = n2; a3 = n3;
            n0 = m0; n1 = m1; n2 = m2; n3 = m3;
            // buf[rr&1] re-scattered at rr+2, after rr+1's barrier: safe.
        }
    } else {
        int blk  = blockIdx.x - ADJ_BLOCKS;              // [0, 2048)
        int warp = (blk * 256 + (int)threadIdx.x) >> 5;  // [0, B*K)
        int lane = threadIdx.x & 31;
        int b    = warp >> 10;
        int idx  = g_topk_idx[warp];
        float g  = tanhf(g_topk_val[warp]);
        const float4* src = reinterpret_cast<const float4*>(
            ne + ((size_t)b * N + idx) * F);
        float4* dst = reinterpret_cast<float4*>(out + (size_t)warp * F);
        float4 v = src[lane];
        v.x *= g; v.y *= g; v.z *= g; v.w *= g;
        dst[lane] = v;
    }
}

// ---------------------------------------------------------------------------
extern "C" void kernel_launch(void* const* d_in, const int* in_sizes, int n_in,
                              void* d_out, int out_size) {
    const float* ne  = (const float*)d_in[0];  // [B,N,F]
    const float* adj = (const float*)d_in[1];  // [B,N,N]
    const float* w   = (const float*)d_in[2];  // [F]
    float* out       = (float*)d_out;

    scores_kernel<<<(B * N) / 32, 256>>>(ne, w);   // 4 rows per warp
    topk_kernel<<<B, 1024>>>();
    fused_kernel<<<ADJ_BLOCKS + (B * K) / 8, 256>>>(ne, adj, out);
}

// round 12
// speedup vs baseline: 1.2819x; 1.0187x over previous
#include <cuda_runtime.h>
#include <stdint.h>

#define B 16
#define N 4096
#define F 128
#define K 1024
#define ROWS_PER_CTA 8
#define ADJ_BLOCKS ((B * K) / ROWS_PER_CTA)   // 2048
#define HB 11
#define NB (1 << HB)   // 2048 histogram buckets

typedef unsigned long long u64;
typedef unsigned int u32;

// scratch (no allocations allowed)
__device__ float g_scores[B * N];
__device__ int   g_topk_idx[B * K];
__device__ float g_topk_val[B * K];
__device__ int   g_scol[B * K];   // selected columns sorted ascending
__device__ int   g_spos[B * K];   // original top-k position of that column

__device__ __forceinline__ unsigned map_f32(float f) {
    unsigned u = __float_as_uint(f);
    return (u & 0x80000000u) ? ~u : (u | 0x80000000u);
}

// ---------------------------------------------------------------------------
// Kernel 1: scores. 4 rows per warp (R7 config, measured 9.3us).
// ---------------------------------------------------------------------------
__global__ void scores_kernel(const float* __restrict__ ne,
                              const float* __restrict__ w) {
    int warp = (blockIdx.x * blockDim.x + threadIdx.x) >> 5;  // [0, B*N/4)
    int lane = threadIdx.x & 31;
    int row0 = warp * 4;
    if (row0 >= B * N) return;

    const float4* wv = reinterpret_cast<const float4*>(w);
    float4 b4 = wv[lane];
    const float4* r0 = reinterpret_cast<const float4*>(ne + (size_t)row0 * F);
    const float4* r1 = reinterpret_cast<const float4*>(ne + (size_t)(row0 + 1) * F);
    const float4* r2 = reinterpret_cast<const float4*>(ne + (size_t)(row0 + 2) * F);
    const float4* r3 = reinterpret_cast<const float4*>(ne + (size_t)(row0 + 3) * F);
    float4 a0 = r0[lane], a1 = r1[lane], a2 = r2[lane], a3 = r3[lane];

    float s0 = a0.x * b4.x + a0.y * b4.y + a0.z * b4.z + a0.w * b4.w;
    float s1 = a1.x * b4.x + a1.y * b4.y + a1.z * b4.z + a1.w * b4.w;
    float s2 = a2.x * b4.x + a2.y * b4.y + a2.z * b4.z + a2.w * b4.w;
    float s3 = a3.x * b4.x + a3.y * b4.y + a3.z * b4.z + a3.w * b4.w;
#pragma unroll
    for (int off = 16; off; off >>= 1) {
        s0 += __shfl_xor_sync(0xffffffffu, s0, off);
        s1 += __shfl_xor_sync(0xffffffffu, s1, off);
        s2 += __shfl_xor_sync(0xffffffffu, s2, off);
        s3 += __shfl_xor_sync(0xffffffffu, s3, off);
    }
    if (lane == 0)
        *reinterpret_cast<float4*>(g_scores + row0) = make_float4(s0, s1, s2, s3);
}

// ---------------------------------------------------------------------------
// Kernel 2: radix-select + 32-bit hybrid bitonic sort + tie-exact ranking.
// Common path sorts the mapped u32 score keys (half the traffic of u64);
// duplicate keys get exact jax order (value desc, index asc) via a
// registration pass. Rare fallback (M > 2048) = full u64 sort, unique keys.
// ---------------------------------------------------------------------------
__device__ __forceinline__ void reg_stages32(u32& e0, u32& e1, int i0, int i1,
                                             int lane, int kk) {
    if (kk >= 64) {
        bool desc = ((i0 & kk) == 0);
        if (desc ? (e0 < e1) : (e0 > e1)) { u32 t = e0; e0 = e1; e1 = t; }
    }
#pragma unroll
    for (int j = 16; j >= 1; j >>= 1) {
        if (j <= (kk >> 1)) {
            bool d0 = ((i0 & kk) == 0);
            bool d1 = ((i1 & kk) == 0);
            bool up = (lane & j) != 0;
            u32 p0 = __shfl_xor_sync(0xffffffffu, e0, j);
            u32 p1 = __shfl_xor_sync(0xffffffffu, e1, j);
            e0 = (d0 ^ up) ? max(e0, p0) : min(e0, p0);
            e1 = (d1 ^ up) ? max(e1, p1) : min(e1, p1);
        }
    }
}

__global__ void __launch_bounds__(1024) topk_kernel() {
    __shared__ u64 candw[4096];      // 32 KB: u32 keys [0:16K) + tiebuf [16K:32K)
    __shared__ int hist[NB];         //  8 KB: histogram -> tie counters -> bitmap
    __shared__ int wsum[32];
    __shared__ int s_t0, s_cnt;

    u32* cand   = (u32*)candw;       // u32 keys, 4096 slots (first 16 KB)
    int* tiebuf = (int*)candw + 4096;// registration buffer (second 16 KB)

    const int b    = blockIdx.x;
    const int tid  = threadIdx.x;
    const int lane = tid & 31;
    const int warp = tid >> 5;
    const float* sc = g_scores + b * N;

    hist[tid] = 0;
    hist[tid + 1024] = 0;
    __syncthreads();

    u32 mreg[4];
#pragma unroll
    for (int q = 0; q < 4; q++) {
        int i = tid + q * 1024;
        mreg[q] = map_f32(sc[i]);
        atomicAdd(&hist[mreg[q] >> (32 - HB)], 1);
    }
    __syncthreads();

    // ---- cutoff bucket t0 = max t such that count(bucket >= t) >= K ----
    {
        int p = hist[2 * tid] + hist[2 * tid + 1];
        int ws = p;
#pragma unroll
        for (int off = 16; off; off >>= 1)
            ws += __shfl_xor_sync(0xffffffffu, ws, off);
        if (lane == 0) wsum[warp] = ws;
    }
    __syncthreads();
    if (warp == 0) {
        int v = wsum[lane];
        int s = v;
#pragma unroll
        for (int off = 1; off < 32; off <<= 1) {
            int t = __shfl_down_sync(0xffffffffu, s, off);
            if (lane + off < 32) s += t;
        }
        unsigned mm = __ballot_sync(0xffffffffu, s >= K);
        int wstar = 31 - __clz(mm);
        int sW = __shfl_sync(0xffffffffu, s, wstar);
        int vW = __shfl_sync(0xffffffffu, v, wstar);
        int run = sW - vW;
        int segbase = wstar * 64;
        int t0 = 0;
#pragma unroll
        for (int c = 1; c >= 0; c--) {
            int bkt = segbase + c * 32 + lane;
            int hv = hist[bkt];
            int s2 = hv;
#pragma unroll
            for (int off = 1; off < 32; off <<= 1) {
                int t = __shfl_down_sync(0xffffffffu, s2, off);
                if (lane + off < 32) s2 += t;
            }
            unsigned m2 = __ballot_sync(0xffffffffu, run + s2 >= K);
            if (m2) { t0 = segbase + c * 32 + (31 - __clz(m2)); break; }
            run += __shfl_sync(0xffffffffu, s2, 0);
        }
        if (lane == 0) { s_t0 = t0; s_cnt = 0; }
    }
    __syncthreads();

    // ---- compact candidate keys (bucket >= t0), warp-aggregated ----
    const int t0 = s_t0;
#pragma unroll
    for (int q = 0; q < 4; q++) {
        bool p = (int)(mreg[q] >> (32 - HB)) >= t0;
        unsigned mask = __ballot_sync(0xffffffffu, p);
        int cnt = __popc(mask);
        int base = 0;
        if (lane == 0 && cnt) base = atomicAdd(&s_cnt, cnt);
        base = __shfl_sync(0xffffffffu, base, 0);
        if (p) cand[base + __popc(mask & ((1u << lane) - 1u))] = mreg[q];
    }
    __syncthreads();
    const int M = s_cnt;

    if (M <= 2048) {
        // ===== common path: 32-bit sort of 2048, tie-exact rank =====
        for (int i = M + tid; i < 2048; i += 1024) cand[i] = 0;  // real keys > 0
        __syncthreads();

        const int base = warp * 64;
        const int i0 = base + lane, i1 = base + 32 + lane;
        u32 e0, e1;

        e0 = cand[i0]; e1 = cand[i1];
#pragma unroll
        for (int kk = 2; kk <= 64; kk <<= 1)
            reg_stages32(e0, e1, i0, i1, lane, kk);
        cand[i0] = e0; cand[i1] = e1;
        __syncthreads();

#pragma unroll
        for (int kk = 128; kk <= 2048; kk <<= 1) {
            for (int j = kk >> 1; j >= 64; j >>= 1) {
                int i = 2 * tid - (tid & (j - 1));
                int x = i + j;
                bool desc = ((i & kk) == 0);
                u32 a = cand[i], c = cand[x];
                if (desc ? (a < c) : (a > c)) { cand[i] = c; cand[x] = a; }
                __syncthreads();
            }
            e0 = cand[i0]; e1 = cand[i1];
            reg_stages32(e0, e1, i0, i1, lane, kk);
            cand[i0] = e0; cand[i1] = e1;
            __syncthreads();
        }

        // re-zero hist as tie counters (indexed by lo < 2048)
        hist[tid] = 0;
        hist[tid + 1024] = 0;
        __syncthreads();

        // registration: each candidate finds first occurrence lo, registers idx
        int loq[4];
#pragma unroll
        for (int q = 0; q < 4; q++) {
            loq[q] = -1;
            if ((int)(mreg[q] >> (32 - HB)) >= t0) {
                u32 m = mreg[q];
                int lo = 0, hi = 2047;       // descending array, m present
                while (lo < hi) {
                    int mid = (lo + hi) >> 1;
                    if (cand[mid] > m) lo = mid + 1; else hi = mid;
                }
                loq[q] = lo;
                int a = atomicAdd(&hist[lo], 1);
                tiebuf[lo + a] = tid + q * 1024;
            }
        }
        __syncthreads();

        // resolve ranks (tie order: ascending original index) and emit
#pragma unroll
        for (int q = 0; q < 4; q++) {
            if (loq[q] >= 0) {
                int lo = loq[q];
                int idx = tid + q * 1024;
                int d = hist[lo];
                int off = 0;
                if (d > 1)
                    for (int j = 0; j < d; j++)
                        off += (tiebuf[lo + j] < idx);
                int rank = lo + off;
                if (rank < K) {
                    u32 m = mreg[q];
                    unsigned u = (m & 0x80000000u) ? (m ^ 0x80000000u) : ~m;
                    g_topk_idx[b * K + rank] = idx;
                    g_topk_val[b * K + rank] = __uint_as_float(u);
                }
            }
        }
    } else {
        // ===== fallback: full u64 sort (keys unique by idx suffix) =====
#pragma unroll
        for (int q = 0; q < 4; q++) {
            int i = tid + q * 1024;
            candw[i] = (((u64)mreg[q]) << 12) | (unsigned)(N - 1 - i);
        }
        __syncthreads();
        for (int kk = 2; kk <= 4096; kk <<= 1) {
            for (int j = kk >> 1; j > 0; j >>= 1) {
                for (int q = tid; q < 2048; q += 1024) {
                    int i = 2 * q - (q & (j - 1));
                    int x = i + j;
                    bool desc = ((i & kk) == 0);
                    u64 a = candw[i], c = candw[x];
                    if (desc ? (a < c) : (a > c)) { candw[i] = c; candw[x] = a; }
                }
                __syncthreads();
            }
        }
        u64 key = candw[tid];          // rank tid < K
        int idx = (N - 1) - (int)(key & 0xFFFu);
        unsigned m = (unsigned)(key >> 12);
        unsigned u = (m & 0x80000000u) ? (m ^ 0x80000000u) : ~m;
        g_topk_idx[b * K + tid] = idx;
        g_topk_val[b * K + tid] = __uint_as_float(u);
    }
    __syncthreads();   // makes g_topk_idx writes visible CTA-wide

    // ---- column-ascending permutation via bitmap counting-rank ----
    // thread tid owns topk position tid: idx2 = g_topk_idx[b*K + tid]
    int idx2 = g_topk_idx[b * K + tid];
    u32* bits = (u32*)hist;           // 4096-bit presence bitmap
    int* wordpref = hist + 128;
    __syncthreads();                  // all reads of hist-as-counters done
    if (tid < 128) bits[tid] = 0;
    __syncthreads();
    atomicOr(&bits[idx2 >> 5], 1u << (idx2 & 31));
    __syncthreads();
    if (warp == 0) {
        int s0 = __popc(bits[4 * lane]);
        int s1 = __popc(bits[4 * lane + 1]);
        int s2 = __popc(bits[4 * lane + 2]);
        int s3 = __popc(bits[4 * lane + 3]);
        int tot = s0 + s1 + s2 + s3;
        int ex = tot;
#pragma unroll
        for (int off = 1; off < 32; off <<= 1) {
            int t = __shfl_up_sync(0xffffffffu, ex, off);
            if (lane >= off) ex += t;
        }
        ex -= tot;
        wordpref[4 * lane]     = ex;
        wordpref[4 * lane + 1] = ex + s0;
        wordpref[4 * lane + 2] = ex + s0 + s1;
        wordpref[4 * lane + 3] = ex + s0 + s1 + s2;
    }
    __syncthreads();
    int wrd = idx2 >> 5, bit = idx2 & 31;
    int rank2 = wordpref[wrd] + __popc(bits[wrd] & ((1u << bit) - 1u));
    g_scol[b * K + rank2] = idx2;
    g_spos[b * K + rank2] = tid;
}

// ---------------------------------------------------------------------------
// Kernel 3 (fused): blocks [0, ADJ_BLOCKS) adj gather (prefetch depth 2);
// blocks [ADJ_BLOCKS, ...) pooled_nodes. (R7 exact)
// ---------------------------------------------------------------------------
__global__ void __launch_bounds__(256) fused_kernel(const float* __restrict__ ne,
                                                    const float* __restrict__ adj,
                                                    float* __restrict__ out) {
    if (blockIdx.x < ADJ_BLOCKS) {
        __shared__ int   scol[K];
        __shared__ short spos[K];
        __shared__ float buf[2][K];
        __shared__ int   ridx[ROWS_PER_CTA];

        float* aout = out + (size_t)B * K * F;
        const int b     = blockIdx.x >> 7;             // 128 CTAs per batch
        const int rbase = (blockIdx.x & 127) * ROWS_PER_CTA;
        const int tid   = threadIdx.x;

#pragma unroll
        for (int q = 0; q < 4; q++) {
            int j = tid + q * 256;
            scol[j] = g_scol[b * K + j];
            spos[j] = (short)g_spos[b * K + j];
        }
        if (tid < ROWS_PER_CTA) ridx[tid] = g_topk_idx[b * K + rbase + tid];
        __syncthreads();

        const int c0 = scol[4 * tid],     c1 = scol[4 * tid + 1];
        const int c2 = scol[4 * tid + 2], c3 = scol[4 * tid + 3];
        const int p0 = spos[4 * tid],     p1 = spos[4 * tid + 1];
        const int p2 = spos[4 * tid + 2], p3 = spos[4 * tid + 3];

        // prefetch rows 0 and 1 (depth-2 pipeline)
        const float* r0 = adj + ((size_t)b * N + ridx[0]) * N;
        float a0 = __ldg(r0 + c0), a1 = __ldg(r0 + c1);
        float a2 = __ldg(r0 + c2), a3 = __ldg(r0 + c3);
        const float* r1 = adj + ((size_t)b * N + ridx[1]) * N;
        float n0 = __ldg(r1 + c0), n1 = __ldg(r1 + c1);
        float n2 = __ldg(r1 + c2), n3 = __ldg(r1 + c3);

#pragma unroll
        for (int rr = 0; rr < ROWS_PER_CTA; rr++) {
            float m0, m1, m2, m3;
            if (rr + 2 < ROWS_PER_CTA) {
                const float* nr = adj + ((size_t)b * N + ridx[rr + 2]) * N;
                m0 = __ldg(nr + c0); m1 = __ldg(nr + c1);
                m2 = __ldg(nr + c2); m3 = __ldg(nr + c3);
            }
            float* bb = buf[rr & 1];
            bb[p0] = a0; bb[p1] = a1; bb[p2] = a2; bb[p3] = a3;
            __syncthreads();
            float4 w = *reinterpret_cast<float4*>(&bb[4 * tid]);
            float* orow = aout + ((size_t)b * K + rbase + rr) * K;
            *reinterpret_cast<float4*>(orow + 4 * tid) = w;
            a0 = n0; a1 = n1; a2 = n2; a3 = n3;
            n0 = m0; n1 = m1; n2 = m2; n3 = m3;
            // buf[rr&1] re-scattered at rr+2, after rr+1's barrier: safe.
        }
    } else {
        int blk  = blockIdx.x - ADJ_BLOCKS;              // [0, 2048)
        int warp = (blk * 256 + (int)threadIdx.x) >> 5;  // [0, B*K)
        int lane = threadIdx.x & 31;
        int b    = warp >> 10;
        int idx  = g_topk_idx[warp];
        float g  = tanhf(g_topk_val[warp]);
        const float4* src = reinterpret_cast<const float4*>(
            ne + ((size_t)b * N + idx) * F);
        float4* dst = reinterpret_cast<float4*>(out + (size_t)warp * F);
        float4 v = src[lane];
        v.x *= g; v.y *= g; v.z *= g; v.w *= g;
        dst[lane] = v;
    }
}

// ---------------------------------------------------------------------------
extern "C" void kernel_launch(void* const* d_in, const int* in_sizes, int n_in,
                              void* d_out, int out_size) {
    const float* ne  = (const float*)d_in[0];  // [B,N,F]
    const float* adj = (const float*)d_in[1];  // [B,N,N]
    const float* w   = (const float*)d_in[2];  // [F]
    float* out       = (float*)d_out;

    scores_kernel<<<(B * N) / 32, 256>>>(ne, w);   // 4 rows per warp
    topk_kernel<<<B, 1024>>>();
    fused_kernel<<<ADJ_BLOCKS + (B * K) / 8, 256>>>(ne, adj, out);
}

// round 13
// speedup vs baseline: 1.3266x; 1.0348x over previous
#include <cuda_runtime.h>
#include <stdint.h>

#define B 16
#define N 4096
#define F 128
#define K 1024
#define ROWS_PER_CTA 8
#define ADJ_BLOCKS ((B * K) / ROWS_PER_CTA)   // 2048
#define HB 11
#define NB (1 << HB)   // 2048 histogram buckets

typedef unsigned long long u64;
typedef unsigned int u32;

// scratch (no allocations allowed)
__device__ float g_scores[B * N];
__device__ int   g_topk_idx[B * K];
__device__ float g_topk_val[B * K];

__device__ __forceinline__ unsigned map_f32(float f) {
    unsigned u = __float_as_uint(f);
    return (u & 0x80000000u) ? ~u : (u | 0x80000000u);
}

// ---------------------------------------------------------------------------
// Kernel 1: scores. 4 rows per warp (R7 config, measured 9.3us).
// ---------------------------------------------------------------------------
__global__ void scores_kernel(const float* __restrict__ ne,
                              const float* __restrict__ w) {
    int warp = (blockIdx.x * blockDim.x + threadIdx.x) >> 5;  // [0, B*N/4)
    int lane = threadIdx.x & 31;
    int row0 = warp * 4;
    if (row0 >= B * N) return;

    const float4* wv = reinterpret_cast<const float4*>(w);
    float4 b4 = wv[lane];
    const float4* r0 = reinterpret_cast<const float4*>(ne + (size_t)row0 * F);
    const float4* r1 = reinterpret_cast<const float4*>(ne + (size_t)(row0 + 1) * F);
    const float4* r2 = reinterpret_cast<const float4*>(ne + (size_t)(row0 + 2) * F);
    const float4* r3 = reinterpret_cast<const float4*>(ne + (size_t)(row0 + 3) * F);
    float4 a0 = r0[lane], a1 = r1[lane], a2 = r2[lane], a3 = r3[lane];

    float s0 = a0.x * b4.x + a0.y * b4.y + a0.z * b4.z + a0.w * b4.w;
    float s1 = a1.x * b4.x + a1.y * b4.y + a1.z * b4.z + a1.w * b4.w;
    float s2 = a2.x * b4.x + a2.y * b4.y + a2.z * b4.z + a2.w * b4.w;
    float s3 = a3.x * b4.x + a3.y * b4.y + a3.z * b4.z + a3.w * b4.w;
#pragma unroll
    for (int off = 16; off; off >>= 1) {
        s0 += __shfl_xor_sync(0xffffffffu, s0, off);
        s1 += __shfl_xor_sync(0xffffffffu, s1, off);
        s2 += __shfl_xor_sync(0xffffffffu, s2, off);
        s3 += __shfl_xor_sync(0xffffffffu, s3, off);
    }
    if (lane == 0)
        *reinterpret_cast<float4*>(g_scores + row0) = make_float4(s0, s1, s2, s3);
}

// ---------------------------------------------------------------------------
// Kernel 2: radix-select + 32-bit hybrid bitonic sort + tie-exact ranking.
// (R12 logic, passing; permutation epilogue removed — no longer needed.)
// ---------------------------------------------------------------------------
__device__ __forceinline__ void reg_stages32(u32& e0, u32& e1, int i0, int i1,
                                             int lane, int kk) {
    if (kk >= 64) {
        bool desc = ((i0 & kk) == 0);
        if (desc ? (e0 < e1) : (e0 > e1)) { u32 t = e0; e0 = e1; e1 = t; }
    }
#pragma unroll
    for (int j = 16; j >= 1; j >>= 1) {
        if (j <= (kk >> 1)) {
            bool d0 = ((i0 & kk) == 0);
            bool d1 = ((i1 & kk) == 0);
            bool up = (lane & j) != 0;
            u32 p0 = __shfl_xor_sync(0xffffffffu, e0, j);
            u32 p1 = __shfl_xor_sync(0xffffffffu, e1, j);
            e0 = (d0 ^ up) ? max(e0, p0) : min(e0, p0);
            e1 = (d1 ^ up) ? max(e1, p1) : min(e1, p1);
        }
    }
}

__global__ void __launch_bounds__(1024) topk_kernel() {
    __shared__ u64 candw[4096];      // 32 KB: u32 keys + tiebuf
    __shared__ int hist[NB];         //  8 KB
    __shared__ int wsum[32];
    __shared__ int s_t0, s_cnt;

    u32* cand   = (u32*)candw;
    int* tiebuf = (int*)candw + 4096;

    const int b    = blockIdx.x;
    const int tid  = threadIdx.x;
    const int lane = tid & 31;
    const int warp = tid >> 5;
    const float* sc = g_scores + b * N;

    hist[tid] = 0;
    hist[tid + 1024] = 0;
    __syncthreads();

    u32 mreg[4];
#pragma unroll
    for (int q = 0; q < 4; q++) {
        int i = tid + q * 1024;
        mreg[q] = map_f32(sc[i]);
        atomicAdd(&hist[mreg[q] >> (32 - HB)], 1);
    }
    __syncthreads();

    // ---- cutoff bucket t0 = max t such that count(bucket >= t) >= K ----
    {
        int p = hist[2 * tid] + hist[2 * tid + 1];
        int ws = p;
#pragma unroll
        for (int off = 16; off; off >>= 1)
            ws += __shfl_xor_sync(0xffffffffu, ws, off);
        if (lane == 0) wsum[warp] = ws;
    }
    __syncthreads();
    if (warp == 0) {
        int v = wsum[lane];
        int s = v;
#pragma unroll
        for (int off = 1; off < 32; off <<= 1) {
            int t = __shfl_down_sync(0xffffffffu, s, off);
            if (lane + off < 32) s += t;
        }
        unsigned mm = __ballot_sync(0xffffffffu, s >= K);
        int wstar = 31 - __clz(mm);
        int sW = __shfl_sync(0xffffffffu, s, wstar);
        int vW = __shfl_sync(0xffffffffu, v, wstar);
        int run = sW - vW;
        int segbase = wstar * 64;
        int t0 = 0;
#pragma unroll
        for (int c = 1; c >= 0; c--) {
            int bkt = segbase + c * 32 + lane;
            int hv = hist[bkt];
            int s2 = hv;
#pragma unroll
            for (int off = 1; off < 32; off <<= 1) {
                int t = __shfl_down_sync(0xffffffffu, s2, off);
                if (lane + off < 32) s2 += t;
            }
            unsigned m2 = __ballot_sync(0xffffffffu, run + s2 >= K);
            if (m2) { t0 = segbase + c * 32 + (31 - __clz(m2)); break; }
            run += __shfl_sync(0xffffffffu, s2, 0);
        }
        if (lane == 0) { s_t0 = t0; s_cnt = 0; }
    }
    __syncthreads();

    // ---- compact candidate keys (bucket >= t0), warp-aggregated ----
    const int t0 = s_t0;
#pragma unroll
    for (int q = 0; q < 4; q++) {
        bool p = (int)(mreg[q] >> (32 - HB)) >= t0;
        unsigned mask = __ballot_sync(0xffffffffu, p);
        int cnt = __popc(mask);
        int base = 0;
        if (lane == 0 && cnt) base = atomicAdd(&s_cnt, cnt);
        base = __shfl_sync(0xffffffffu, base, 0);
        if (p) cand[base + __popc(mask & ((1u << lane) - 1u))] = mreg[q];
    }
    __syncthreads();
    const int M = s_cnt;

    if (M <= 2048) {
        // ===== common path: 32-bit sort of 2048, tie-exact rank =====
        for (int i = M + tid; i < 2048; i += 1024) cand[i] = 0;  // real keys > 0
        __syncthreads();

        const int base = warp * 64;
        const int i0 = base + lane, i1 = base + 32 + lane;
        u32 e0, e1;

        e0 = cand[i0]; e1 = cand[i1];
#pragma unroll
        for (int kk = 2; kk <= 64; kk <<= 1)
            reg_stages32(e0, e1, i0, i1, lane, kk);
        cand[i0] = e0; cand[i1] = e1;
        __syncthreads();

#pragma unroll
        for (int kk = 128; kk <= 2048; kk <<= 1) {
            for (int j = kk >> 1; j >= 64; j >>= 1) {
                int i = 2 * tid - (tid & (j - 1));
                int x = i + j;
                bool desc = ((i & kk) == 0);
                u32 a = cand[i], c = cand[x];
                if (desc ? (a < c) : (a > c)) { cand[i] = c; cand[x] = a; }
                __syncthreads();
            }
            e0 = cand[i0]; e1 = cand[i1];
            reg_stages32(e0, e1, i0, i1, lane, kk);
            cand[i0] = e0; cand[i1] = e1;
            __syncthreads();
        }

        // re-zero hist as tie counters
        hist[tid] = 0;
        hist[tid + 1024] = 0;
        __syncthreads();

        // registration: each candidate finds first occurrence lo, registers idx
        int loq[4];
#pragma unroll
        for (int q = 0; q < 4; q++) {
            loq[q] = -1;
            if ((int)(mreg[q] >> (32 - HB)) >= t0) {
                u32 m = mreg[q];
                int lo = 0, hi = 2047;       // descending array, m present
                while (lo < hi) {
                    int mid = (lo + hi) >> 1;
                    if (cand[mid] > m) lo = mid + 1; else hi = mid;
                }
                loq[q] = lo;
                int a = atomicAdd(&hist[lo], 1);
                tiebuf[lo + a] = tid + q * 1024;
            }
        }
        __syncthreads();

        // resolve ranks (tie order: ascending original index) and emit
#pragma unroll
        for (int q = 0; q < 4; q++) {
            if (loq[q] >= 0) {
                int lo = loq[q];
                int idx = tid + q * 1024;
                int d = hist[lo];
                int off = 0;
                if (d > 1)
                    for (int j = 0; j < d; j++)
                        off += (tiebuf[lo + j] < idx);
                int rank = lo + off;
                if (rank < K) {
                    u32 m = mreg[q];
                    unsigned u = (m & 0x80000000u) ? (m ^ 0x80000000u) : ~m;
                    g_topk_idx[b * K + rank] = idx;
                    g_topk_val[b * K + rank] = __uint_as_float(u);
                }
            }
        }
    } else {
        // ===== fallback: full u64 sort (keys unique by idx suffix) =====
#pragma unroll
        for (int q = 0; q < 4; q++) {
            int i = tid + q * 1024;
            candw[i] = (((u64)mreg[q]) << 12) | (unsigned)(N - 1 - i);
        }
        __syncthreads();
        for (int kk = 2; kk <= 4096; kk <<= 1) {
            for (int j = kk >> 1; j > 0; j >>= 1) {
                for (int q = tid; q < 2048; q += 1024) {
                    int i = 2 * q - (q & (j - 1));
                    int x = i + j;
                    bool desc = ((i & kk) == 0);
                    u64 a = candw[i], c = candw[x];
                    if (desc ? (a < c) : (a > c)) { candw[i] = c; candw[x] = a; }
                }
                __syncthreads();
            }
        }
        u64 key = candw[tid];          // rank tid < K
        int idx = (N - 1) - (int)(key & 0xFFFu);
        unsigned m = (unsigned)(key >> 12);
        unsigned u = (m & 0x80000000u) ? (m ^ 0x80000000u) : ~m;
        g_topk_idx[b * K + tid] = idx;
        g_topk_val[b * K + tid] = __uint_as_float(u);
    }
}

// ---------------------------------------------------------------------------
// cp.async helpers
// ---------------------------------------------------------------------------
__device__ __forceinline__ void cp16(u32 smem_addr, const void* gmem) {
    asm volatile("cp.async.cg.shared.global [%0], [%1], 16;"
                 :: "r"(smem_addr), "l"(gmem));
}
__device__ __forceinline__ void cp_commit() {
    asm volatile("cp.async.commit_group;" ::: "memory");
}
__device__ __forceinline__ void cp_wait0() {
    asm volatile("cp.async.wait_group 0;" ::: "memory");
}

// ---------------------------------------------------------------------------
// Kernel 3 (fused):
//  blocks [0, ADJ_BLOCKS): pooled_adj via FULL-ROW STREAMING. Each needed
//  16KB adjacency row is cp.async-streamed (coalesced, ~same bytes as the
//  86%-of-sectors gather but at streaming DRAM efficiency) into a
//  double-buffered smem row; threads pick their 4 columns in topk order
//  directly from smem and store one coalesced float4.
//  blocks [ADJ_BLOCKS, ...): pooled_nodes (unchanged).
// ---------------------------------------------------------------------------
__global__ void __launch_bounds__(256) fused_kernel(const float* __restrict__ ne,
                                                    const float* __restrict__ adj,
                                                    float* __restrict__ out) {
    if (blockIdx.x < ADJ_BLOCKS) {
        __shared__ __align__(16) float rowbuf[2][N];   // 32 KB
        __shared__ __align__(16) int   cidx[K];        //  4 KB (topk order)
        __shared__ int ridx[ROWS_PER_CTA];

        float* aout = out + (size_t)B * K * F;
        const int b     = blockIdx.x >> 7;             // 128 CTAs per batch
        const int rbase = (blockIdx.x & 127) * ROWS_PER_CTA;
        const int tid   = threadIdx.x;

#pragma unroll
        for (int q = 0; q < 4; q++)
            cidx[tid + q * 256] = g_topk_idx[b * K + tid + q * 256];
        if (tid < ROWS_PER_CTA) ridx[tid] = g_topk_idx[b * K + rbase + tid];
        __syncthreads();

        int4 cc = *reinterpret_cast<int4*>(&cidx[4 * tid]);

        // preload row 0: 4 x 16B chunks per thread, coalesced
        {
            const char* g = (const char*)(adj + ((size_t)b * N + ridx[0]) * N);
            u32 s = (u32)__cvta_generic_to_shared(rowbuf[0]);
#pragma unroll
            for (int k2 = 0; k2 < 4; k2++)
                cp16(s + (tid + k2 * 256) * 16, g + (tid + k2 * 256) * 16);
            cp_commit();
        }

#pragma unroll
        for (int rr = 0; rr < ROWS_PER_CTA; rr++) {
            cp_wait0();
            __syncthreads();            // row rr visible to all threads
            if (rr + 1 < ROWS_PER_CTA) {
                // issue row rr+1 into the other buffer (its readers finished
                // at iter rr-1, before this iteration's barrier)
                const char* g = (const char*)(adj +
                                ((size_t)b * N + ridx[rr + 1]) * N);
                u32 s = (u32)__cvta_generic_to_shared(rowbuf[(rr + 1) & 1]);
#pragma unroll
                for (int k2 = 0; k2 < 4; k2++)
                    cp16(s + (tid + k2 * 256) * 16, g + (tid + k2 * 256) * 16);
                cp_commit();
            }
            const float* rb = rowbuf[rr & 1];
            float4 v = make_float4(rb[cc.x], rb[cc.y], rb[cc.z], rb[cc.w]);
            float* orow = aout + ((size_t)b * K + rbase + rr) * K;
            *reinterpret_cast<float4*>(orow + 4 * tid) = v;
        }
    } else {
        int blk  = blockIdx.x - ADJ_BLOCKS;              // [0, 2048)
        int warp = (blk * 256 + (int)threadIdx.x) >> 5;  // [0, B*K)
        int lane = threadIdx.x & 31;
        int b    = warp >> 10;
        int idx  = g_topk_idx[warp];
        float g  = tanhf(g_topk_val[warp]);
        const float4* src = reinterpret_cast<const float4*>(
            ne + ((size_t)b * N + idx) * F);
        float4* dst = reinterpret_cast<float4*>(out + (size_t)warp * F);
        float4 v = src[lane];
        v.x *= g; v.y *= g; v.z *= g; v.w *= g;
        dst[lane] = v;
    }
}

// ---------------------------------------------------------------------------
extern "C" void kernel_launch(void* const* d_in, const int* in_sizes, int n_in,
                              void* d_out, int out_size) {
    const float* ne  = (const float*)d_in[0];  // [B,N,F]
    const float* adj = (const float*)d_in[1];  // [B,N,N]
    const float* w   = (const float*)d_in[2];  // [F]
    float* out       = (float*)d_out;

    scores_kernel<<<(B * N) / 32, 256>>>(ne, w);   // 4 rows per warp
    topk_kernel<<<B, 1024>>>();
    fused_kernel<<<ADJ_BLOCKS + (B * K) / 8, 256>>>(ne, adj, out);
}